// round 1
// baseline (speedup 1.0000x reference)
#include <cuda_runtime.h>
#include <cuda_bf16.h>
#include <math.h>

// Problem constants (fixed shapes for this bench)
constexpr int Bc  = 4;
constexpr int Lc  = 2048;
constexpr int Dc  = 512;
constexpr int Hc  = 8;
constexpr int DKc = 64;
constexpr int UMAX = 64;   // safety cap for top-k storage (actual U = 40)

// ---------------- scratch (device globals; no allocation allowed) ------------
__device__ float g_Q[Bc*Hc*Lc*DKc];      // (b,h,l,d)  16 MB
__device__ float g_K[Bc*Hc*Lc*DKc];      // 16 MB
__device__ float g_V[Bc*Hc*Lc*DKc];      // 16 MB
__device__ float g_ctx[Bc*Lc*Dc];        // (b,l,h,d) = (b,l,D)  16 MB
__device__ float g_M[Bc*Hc*Lc];          // sparsity measure
__device__ int   g_top[Bc*Hc*UMAX];      // top-u indices per (b,h)
__device__ float g_vmean[Bc*Hc*DKc];     // V mean over L

// ---------------- SGEMM: out = X[M,K] @ W[N,K]^T + bias ---------------------
// BM=128, BN=64, BK=16, 256 threads, 8x4 microtile.
// permute=0: out[m*N+n] ; permute=1: out[((b*H+h)*L+l)*dk+d] with m=(b,l), n=(h,d)
__global__ __launch_bounds__(256) void sgemm_bias_kernel(
    const float* __restrict__ X, const float* __restrict__ W,
    const float* __restrict__ bias, float* __restrict__ out, int permute)
{
    constexpr int N = Dc, K = Dc;
    constexpr int BM = 128, BN = 64, BK = 16;
    __shared__ float As[BK][BM + 4];
    __shared__ float Bs[BK][BN + 4];

    const int m0 = blockIdx.y * BM;
    const int n0 = blockIdx.x * BN;
    const int tid = threadIdx.x;
    const int tx = tid & 15;   // n-dim, 0..15
    const int ty = tid >> 4;   // m-dim, 0..15

    float acc[8][4];
    #pragma unroll
    for (int i = 0; i < 8; i++)
        #pragma unroll
        for (int j = 0; j < 4; j++) acc[i][j] = 0.0f;

    for (int k0 = 0; k0 < K; k0 += BK) {
        // load A tile: 128x16 floats = 512 float4 (2 per thread)
        #pragma unroll
        for (int i = 0; i < 2; i++) {
            int t  = tid + i * 256;
            int r  = t >> 2;
            int c4 = (t & 3) * 4;
            float4 v = *reinterpret_cast<const float4*>(X + (size_t)(m0 + r) * K + k0 + c4);
            As[c4 + 0][r] = v.x; As[c4 + 1][r] = v.y;
            As[c4 + 2][r] = v.z; As[c4 + 3][r] = v.w;
        }
        // load W tile: 64x16 floats = 256 float4 (1 per thread), store transposed
        {
            int r  = tid >> 2;
            int c4 = (tid & 3) * 4;
            float4 v = *reinterpret_cast<const float4*>(W + (size_t)(n0 + r) * K + k0 + c4);
            Bs[c4 + 0][r] = v.x; Bs[c4 + 1][r] = v.y;
            Bs[c4 + 2][r] = v.z; Bs[c4 + 3][r] = v.w;
        }
        __syncthreads();

        #pragma unroll
        for (int k = 0; k < BK; k++) {
            float4 a0 = *reinterpret_cast<const float4*>(&As[k][ty * 8]);
            float4 a1 = *reinterpret_cast<const float4*>(&As[k][ty * 8 + 4]);
            float4 b0 = *reinterpret_cast<const float4*>(&Bs[k][tx * 4]);
            float a[8] = {a0.x, a0.y, a0.z, a0.w, a1.x, a1.y, a1.z, a1.w};
            float bb[4] = {b0.x, b0.y, b0.z, b0.w};
            #pragma unroll
            for (int i = 0; i < 8; i++)
                #pragma unroll
                for (int j = 0; j < 4; j++)
                    acc[i][j] = fmaf(a[i], bb[j], acc[i][j]);
        }
        __syncthreads();
    }

    #pragma unroll
    for (int i = 0; i < 8; i++) {
        int m = m0 + ty * 8 + i;
        int b = m >> 11;         // / 2048
        int l = m & 2047;
        #pragma unroll
        for (int j = 0; j < 4; j++) {
            int n = n0 + tx * 4 + j;
            float v = acc[i][j] + bias[n];
            if (!permute) {
                out[(size_t)m * N + n] = v;
            } else {
                int h = n >> 6, d = n & 63;
                out[(((size_t)(b * Hc + h)) * Lc + l) * DKc + d] = v;
            }
        }
    }
}

// ---------------- V mean over L per (b,h,d) ----------------------------------
__global__ __launch_bounds__(256) void vmean_kernel()
{
    int bh  = blockIdx.x;
    int tid = threadIdx.x;
    int d   = tid & 63;
    int seg = tid >> 6;   // 0..3
    const float* Vb = g_V + (size_t)bh * Lc * DKc;
    float acc = 0.0f;
    for (int l = seg * 512; l < seg * 512 + 512; ++l)
        acc += Vb[(size_t)l * 64 + d];
    __shared__ float red[256];
    red[tid] = acc;
    __syncthreads();
    if (seg == 0)
        g_vmean[bh * 64 + d] =
            (red[d] + red[d + 64] + red[d + 128] + red[d + 192]) * (1.0f / Lc);
}

// ---------------- QK_sample + M measure (one warp per (b,h,q)) ---------------
__global__ __launch_bounds__(256) void qk_sample_kernel(const int* __restrict__ idxs, int U)
{
    int warp = (blockIdx.x * blockDim.x + threadIdx.x) >> 5;
    int lane = threadIdx.x & 31;
    if (warp >= Bc * Hc * Lc) return;
    int q  = warp % Lc;
    int bh = warp / Lc;

    const float* Qr = g_Q + ((size_t)bh * Lc + q) * 64;
    float q0 = Qr[lane], q1 = Qr[lane + 32];

    float mx = -1e30f, sm = 0.0f;
    for (int j = 0; j < U; j++) {
        int ki = idxs[q * U + j];
        const float* Kr = g_K + ((size_t)bh * Lc + ki) * 64;
        float p = q0 * Kr[lane] + q1 * Kr[lane + 32];
        #pragma unroll
        for (int o = 16; o > 0; o >>= 1) p += __shfl_xor_sync(0xFFFFFFFFu, p, o);
        mx = fmaxf(mx, p);
        sm += p;
    }
    if (lane == 0) g_M[(size_t)bh * Lc + q] = mx - sm * (1.0f / (float)Lc);
}

// ---------------- top-U per (b,h): iterative argmax over 2048 ----------------
__global__ __launch_bounds__(256) void topk_kernel(int U)
{
    int bh  = blockIdx.x;
    int tid = threadIdx.x;
    __shared__ float vals[Lc];
    __shared__ float rmax[256];
    __shared__ int   ridx[256];

    for (int i = tid; i < Lc; i += 256) vals[i] = g_M[(size_t)bh * Lc + i];
    __syncthreads();

    for (int it = 0; it < U; it++) {
        float best = -1e30f; int bi = Lc;
        for (int i = tid; i < Lc; i += 256) {
            float v = vals[i];
            if (v > best) { best = v; bi = i; }
        }
        rmax[tid] = best; ridx[tid] = bi;
        __syncthreads();
        for (int s = 128; s > 0; s >>= 1) {
            if (tid < s) {
                if (rmax[tid + s] > rmax[tid] ||
                    (rmax[tid + s] == rmax[tid] && ridx[tid + s] < ridx[tid])) {
                    rmax[tid] = rmax[tid + s];
                    ridx[tid] = ridx[tid + s];
                }
            }
            __syncthreads();
        }
        if (tid == 0) {
            g_top[bh * UMAX + it] = ridx[0];
            vals[ridx[0]] = -1e30f;
        }
        __syncthreads();
    }
}

// ---------------- fill context with broadcast V-mean -------------------------
__global__ __launch_bounds__(256) void fill_ctx_kernel()
{
    size_t i = (size_t)blockIdx.x * 256 + threadIdx.x;  // over B*L*D
    int d = (int)(i & 63);
    int h = (int)((i >> 6) & 7);
    int b = (int)(i >> 20);                              // L*H*64 = 2^20
    g_ctx[i] = g_vmean[(b * Hc + h) * 64 + d];
}

// ---------------- dense attention for the top-u queries + scatter ------------
__global__ __launch_bounds__(256) void sparse_attn_kernel()
{
    int bh = blockIdx.x;
    int ui = blockIdx.y;
    int b  = bh / Hc, h = bh % Hc;
    int lq = g_top[bh * UMAX + ui];
    int tid = threadIdx.x;

    __shared__ float qv[64];
    __shared__ float probs[Lc];
    __shared__ float red[256];

    if (tid < 64) qv[tid] = g_Q[((size_t)bh * Lc + lq) * 64 + tid];
    __syncthreads();

    const float scale = 0.125f;  // 1/sqrt(64)
    float s[8];
    float lmax = -1e30f;
    #pragma unroll
    for (int c = 0; c < 8; c++) {
        int k = tid + c * 256;
        const float4* Kr = reinterpret_cast<const float4*>(g_K + ((size_t)bh * Lc + k) * 64);
        float acc = 0.0f;
        #pragma unroll
        for (int d4 = 0; d4 < 16; d4++) {
            float4 kv = Kr[d4];
            acc = fmaf(kv.x, qv[d4 * 4 + 0], acc);
            acc = fmaf(kv.y, qv[d4 * 4 + 1], acc);
            acc = fmaf(kv.z, qv[d4 * 4 + 2], acc);
            acc = fmaf(kv.w, qv[d4 * 4 + 3], acc);
        }
        s[c] = acc * scale;
        lmax = fmaxf(lmax, s[c]);
    }

    // block max
    red[tid] = lmax; __syncthreads();
    for (int st = 128; st > 0; st >>= 1) {
        if (tid < st) red[tid] = fmaxf(red[tid], red[tid + st]);
        __syncthreads();
    }
    float m = red[0];
    __syncthreads();

    float lsum = 0.0f;
    #pragma unroll
    for (int c = 0; c < 8; c++) {
        float e = expf(s[c] - m);
        probs[tid + c * 256] = e;
        lsum += e;
    }
    red[tid] = lsum; __syncthreads();
    for (int st = 128; st > 0; st >>= 1) {
        if (tid < st) red[tid] += red[tid + st];
        __syncthreads();
    }
    float inv = 1.0f / red[0];
    __syncthreads();

    // context_in = probs @ V : thread = (d, key-chunk)
    int d  = tid & 63;
    int ch = tid >> 6;  // 0..3
    float acc = 0.0f;
    const float* Vb = g_V + (size_t)bh * Lc * 64;
    for (int k = ch * 512; k < ch * 512 + 512; k++)
        acc = fmaf(probs[k], Vb[(size_t)k * 64 + d], acc);
    red[tid] = acc;
    __syncthreads();
    if (ch == 0) {
        float t = red[d] + red[d + 64] + red[d + 128] + red[d + 192];
        g_ctx[(((size_t)(b * Lc + lq)) * Hc + h) * 64 + d] = t * inv;
    }
}

// ---------------- launch ------------------------------------------------------
extern "C" void kernel_launch(void* const* d_in, const int* in_sizes, int n_in,
                              void* d_out, int out_size)
{
    const float* queries = (const float*)d_in[0];
    const float* keys    = (const float*)d_in[1];
    const float* values  = (const float*)d_in[2];
    const float* Wq = (const float*)d_in[3];
    const float* bq = (const float*)d_in[4];
    const float* Wk = (const float*)d_in[5];
    const float* bk = (const float*)d_in[6];
    const float* Wv = (const float*)d_in[7];
    const float* bv = (const float*)d_in[8];
    const float* Wo = (const float*)d_in[9];
    const float* bo = (const float*)d_in[10];
    const int* index_sample = (const int*)d_in[11];

    int U = in_sizes[11] / Lc;   // 40 for this bench
    if (U > UMAX) U = UMAX;

    float *qp, *kp, *vp, *ctx;
    cudaGetSymbolAddress((void**)&qp,  g_Q);
    cudaGetSymbolAddress((void**)&kp,  g_K);
    cudaGetSymbolAddress((void**)&vp,  g_V);
    cudaGetSymbolAddress((void**)&ctx, g_ctx);

    dim3 ggrid(Dc / 64, (Bc * Lc) / 128);  // (8, 64)

    // projections -> (b,h,l,d)
    sgemm_bias_kernel<<<ggrid, 256>>>(queries, Wq, bq, qp, 1);
    sgemm_bias_kernel<<<ggrid, 256>>>(keys,    Wk, bk, kp, 1);
    sgemm_bias_kernel<<<ggrid, 256>>>(values,  Wv, bv, vp, 1);

    vmean_kernel<<<Bc * Hc, 256>>>();

    int warps = Bc * Hc * Lc;
    qk_sample_kernel<<<(warps * 32) / 256, 256>>>(index_sample, U);

    topk_kernel<<<Bc * Hc, 256>>>(U);

    fill_ctx_kernel<<<(Bc * Lc * Dc) / 256, 256>>>();

    sparse_attn_kernel<<<dim3(Bc * Hc, U), 256>>>();

    // output projection -> plain (b,l,D)
    sgemm_bias_kernel<<<ggrid, 256>>>(ctx, Wo, bo, (float*)d_out, 0);
}